// round 10
// baseline (speedup 1.0000x reference)
#include <cuda_runtime.h>
#include <cuda_fp16.h>
#include <math.h>

#define BB 512
#define TT 512

// ---------------- device scratch (allocation-free rule) ----------------
__device__ __half g_gxh[(size_t)TT * BB * 512];   // gate pre-activations (fp16)
__device__ __half g_h1[(size_t)BB * TT * 32];     // layer1 output (fp16)
__device__ __half g_h2[(size_t)BB * TT * 48];     // layer2 output (fp16)
__device__ float  g_Wt3[128 * 512];               // Whh3 transposed [k][col]

// ---------------- f32x2 helpers ----------------
__device__ __forceinline__ unsigned long long pk2(float a, float b) {
    unsigned long long r;
    asm("mov.b64 %0, {%1,%2};" : "=l"(r) : "f"(a), "f"(b));
    return r;
}
__device__ __forceinline__ void fma2_(unsigned long long& d, unsigned long long a,
                                      unsigned long long b) {
    asm("fma.rn.f32x2 %0, %1, %2, %0;" : "+l"(d) : "l"(a), "l"(b));
}
__device__ __forceinline__ unsigned long long add2_(unsigned long long a,
                                                    unsigned long long b) {
    unsigned long long r;
    asm("add.rn.f32x2 %0, %1, %2;" : "=l"(r) : "l"(a), "l"(b));
    return r;
}
__device__ __forceinline__ float sig_(float x) { return 1.0f / (1.0f + __expf(-x)); }
__device__ __forceinline__ float th_(float x) { return 1.0f - 2.0f / (__expf(2.0f * x) + 1.0f); }

// ---------------- mma helpers (verified in R8) ----------------
__device__ __forceinline__ unsigned smem_u32(const void* p) {
    return (unsigned)__cvta_generic_to_shared(p);
}
__device__ __forceinline__ void ldmx4(unsigned& a0, unsigned& a1, unsigned& a2,
                                      unsigned& a3, unsigned addr) {
    asm volatile("ldmatrix.sync.aligned.m8n8.x4.shared.b16 {%0,%1,%2,%3}, [%4];"
                 : "=r"(a0), "=r"(a1), "=r"(a2), "=r"(a3) : "r"(addr));
}
__device__ __forceinline__ void mma16816(float* d, unsigned a0, unsigned a1,
                                         unsigned a2, unsigned a3,
                                         unsigned b0, unsigned b1) {
    asm volatile(
        "mma.sync.aligned.m16n8k16.row.col.f32.f16.f16.f32 "
        "{%0,%1,%2,%3}, {%4,%5,%6,%7}, {%8,%9}, {%0,%1,%2,%3};"
        : "+f"(d[0]), "+f"(d[1]), "+f"(d[2]), "+f"(d[3])
        : "r"(a0), "r"(a1), "r"(a2), "r"(a3), "r"(b0), "r"(b1));
}

// ---------------------------------------------------------------------------
// Input projection via tensor cores: gx[t][b][:] = x[b][t][:] @ Wih^T + bias.
// 256 threads (8 warps), 32 rows/tile; warp owns N/8 gate cols.
// Wih held as B-fragments in registers for the whole block (tile loop).
// XF32: x is fp32 (layer-1 z); else fp16.
// ---------------------------------------------------------------------------
template <int D, int N, bool XF32>
__global__ void __launch_bounds__(256)
lstm_projM(const void* __restrict__ xin, const float* __restrict__ Wih,
           const float* __restrict__ bih, const float* __restrict__ bhh,
           __half* __restrict__ gx)
{
    constexpr int KT = D / 16;        // k-tiles
    constexpr int NTILES = N / 64;    // n-tiles of 8 per warp (8 warps)
    constexpr int NCW = N / 8;        // cols per warp
    constexpr int XPAD = D + 8;

    __shared__ __align__(16) __half xs[32][XPAD];

    const int tid = threadIdx.x;
    const int w = tid >> 5, l = tid & 31;
    const int l4 = l & 3, lq = l >> 2;
    const int wbase = w * NCW;

    // B fragments from Wih [N][D] row-major == col-major [D x N] for row.col
    unsigned bf[KT][NTILES][2];
#pragma unroll
    for (int kt = 0; kt < KT; kt++)
#pragma unroll
        for (int ti = 0; ti < NTILES; ti++) {
            int n = wbase + ti * 8 + lq;
            int k0 = kt * 16 + 2 * l4;
            __half2 v0 = __floats2half2_rn(__ldg(&Wih[n * D + k0]),
                                           __ldg(&Wih[n * D + k0 + 1]));
            __half2 v1 = __floats2half2_rn(__ldg(&Wih[n * D + k0 + 8]),
                                           __ldg(&Wih[n * D + k0 + 9]));
            bf[kt][ti][0] = *(unsigned*)&v0;
            bf[kt][ti][1] = *(unsigned*)&v1;
        }
    float2 b2[NTILES];
#pragma unroll
    for (int ti = 0; ti < NTILES; ti++) {
        int n0 = wbase + ti * 8 + 2 * l4;
        b2[ti] = make_float2(__ldg(&bih[n0]) + __ldg(&bhh[n0]),
                             __ldg(&bih[n0 + 1]) + __ldg(&bhh[n0 + 1]));
    }

    const int arow = l & 15, acg = (l >> 4) * 8;
    const int ntiles_tot = (BB * TT) / 32;

#pragma unroll 1
    for (int tile = blockIdx.x; tile < ntiles_tot; tile += gridDim.x) {
        __syncthreads();
        if (XF32) {
            const float* xf = (const float*)xin;
#pragma unroll 1
            for (int i = tid; i < 32 * (D / 4); i += 256) {
                int row = i / (D / 4), k4 = i % (D / 4);
                float4 v = ((const float4*)(xf + (size_t)(tile * 32 + row) * D))[k4];
                *(__half2*)&xs[row][4 * k4]     = __floats2half2_rn(v.x, v.y);
                *(__half2*)&xs[row][4 * k4 + 2] = __floats2half2_rn(v.z, v.w);
            }
        } else {
            const __half* xh = (const __half*)xin;
#pragma unroll 1
            for (int i = tid; i < 32 * (D / 8); i += 256) {
                int row = i / (D / 8), k8 = i % (D / 8);
                float4 v = ((const float4*)(xh + (size_t)(tile * 32 + row) * D))[k8];
                *(float4*)&xs[row][8 * k8] = v;
            }
        }
        __syncthreads();

#pragma unroll
        for (int mt = 0; mt < 2; mt++) {
            unsigned aa[KT][4];
#pragma unroll
            for (int kt = 0; kt < KT; kt++)
                ldmx4(aa[kt][0], aa[kt][1], aa[kt][2], aa[kt][3],
                      smem_u32(&xs[mt * 16 + arow][acg + 16 * kt]));

            float d[NTILES][4];
#pragma unroll
            for (int ti = 0; ti < NTILES; ti++) {
                d[ti][0] = b2[ti].x; d[ti][1] = b2[ti].y;
                d[ti][2] = b2[ti].x; d[ti][3] = b2[ti].y;
            }
#pragma unroll
            for (int kt = 0; kt < KT; kt++)
#pragma unroll
                for (int ti = 0; ti < NTILES; ti++)
                    mma16816(d[ti], aa[kt][0], aa[kt][1], aa[kt][2], aa[kt][3],
                             bf[kt][ti][0], bf[kt][ti][1]);

#pragma unroll
            for (int ti = 0; ti < NTILES; ti++)
#pragma unroll
                for (int rr = 0; rr < 2; rr++) {
                    int m = tile * 32 + mt * 16 + lq + 8 * rr;
                    int b = m >> 9, t = m & 511;
                    int col = wbase + ti * 8 + 2 * l4;
                    *(__half2*)(gx + ((size_t)t * BB + b) * N + col) =
                        __floats2half2_rn(d[ti][2 * rr], d[ti][2 * rr + 1]);
                }
        }
    }
}

// ---------------------------------------------------------------------------
// Small-layer recurrence (R4-proven), fp16 gx, depth-2 prefetch, fp16 out.
// ---------------------------------------------------------------------------
template <int H>
__global__ void __launch_bounds__(4 * H)
lstm_recur_small(const __half* __restrict__ gx,  // [T][B][4H] fp16
                 const float* __restrict__ Whh,  // [4H][H]
                 __half* __restrict__ out)       // [B][T][H] fp16
{
    constexpr int G = 4 * H;
    const int col = threadIdx.x;
    const int b0 = blockIdx.x * 2;

    unsigned long long wh2[H];
#pragma unroll
    for (int k = 0; k < H; k++) {
        float w = __ldg(&Whh[col * H + k]);
        wh2[k] = pk2(w, w);
    }

    __shared__ unsigned long long h2[H];
    __shared__ unsigned long long g2[G];
    if (col < H) h2[col] = 0ull;

    const int erow = col & 1, ecol = col >> 1;
    float c = 0.f;

    const __half* gbase = gx + (size_t)b0 * G + col;
    const size_t tstride = (size_t)BB * G;

    __half A0 = gbase[0], A1 = gbase[G];
    __half B0 = gbase[tstride], B1 = gbase[tstride + G];
    __syncthreads();

    for (int t = 0; t < TT; t++) {
        __half C0 = __float2half(0.f), C1 = C0;
        if (t + 2 < TT) {
            const __half* gp = gbase + (size_t)(t + 2) * tstride;
            C0 = gp[0]; C1 = gp[G];
        }
        unsigned long long a0 = 0ull, a1 = 0ull, a2 = 0ull, a3 = 0ull;
#pragma unroll
        for (int k = 0; k < H; k += 4) {
            fma2_(a0, wh2[k + 0], h2[k + 0]);
            fma2_(a1, wh2[k + 1], h2[k + 1]);
            fma2_(a2, wh2[k + 2], h2[k + 2]);
            fma2_(a3, wh2[k + 3], h2[k + 3]);
        }
        g2[col] = add2_(add2_(add2_(a0, a1), add2_(a2, a3)),
                        pk2(__half2float(A0), __half2float(A1)));
        A0 = B0; A1 = B1; B0 = C0; B1 = C1;
        __syncthreads();

        if (col < 2 * H) {
            const float* gf = (const float*)g2;
            float gi = gf[2 * ecol + erow];
            float gF = gf[2 * (H + ecol) + erow];
            float gg = gf[2 * (2 * H + ecol) + erow];
            float go = gf[2 * (3 * H + ecol) + erow];
            c = sig_(gF) * c + sig_(gi) * th_(gg);
            float h = sig_(go) * th_(c);
            ((float*)h2)[2 * ecol + erow] = h;
            out[((size_t)(b0 + erow) * TT + t) * H + ecol] = __float2half(h);
        }
        __syncthreads();
    }
}

// ---------------------------------------------------------------------------
// Layer-3 recurrence (R4-proven): KSM=96 k-rows in smem, 32 in registers.
// ---------------------------------------------------------------------------
#define KSM 96
#define KRG (128 - KSM)
#define SMEM_BIG (KSM * 512 * 4 + 128 * 16 + 512 * 16)   // 206,848 B

__global__ void __launch_bounds__(256)
lstm_recur_big(const __half* __restrict__ gx,  // [T][B][512] fp16
               const float* __restrict__ Wt,   // [128][512] transposed Whh3
               float* __restrict__ out,        // [B][T][128]
               float* __restrict__ hn)         // [B][128]
{
    extern __shared__ char sraw[];
    float2* Wsm = (float2*)sraw;                                         // [KSM][256]
    unsigned long long* hp = (unsigned long long*)(sraw + KSM * 512 * 4);        // [128][2]
    unsigned long long* g4 = (unsigned long long*)(sraw + KSM * 512 * 4 + 2048); // [512][2]

    const int tid = threadIdx.x;
    const int b0 = blockIdx.x * 4;
    const int c0 = tid * 2;

    for (int i = tid; i < KSM * 128; i += 256)
        ((float4*)Wsm)[i] = ((const float4*)Wt)[i];
    float2 wg[KRG];
#pragma unroll
    for (int j = 0; j < KRG; j++)
        wg[j] = *(const float2*)(Wt + (size_t)(KSM + j) * 512 + c0);

    hp[tid] = 0ull;

    const int ecol = tid & 127, erp = tid >> 7;
    float cA = 0.f, cB = 0.f;

    const __half2* gb = (const __half2*)(gx + (size_t)b0 * 512 + c0);
    const size_t tstride = (size_t)BB * 256;   // in half2 units

    __half2 pA0 = gb[0], pA1 = gb[256], pA2 = gb[512], pA3 = gb[768];
    __half2 pB0 = gb[tstride + 0], pB1 = gb[tstride + 256],
            pB2 = gb[tstride + 512], pB3 = gb[tstride + 768];
    __syncthreads();

    const ulonglong2* hp2 = (const ulonglong2*)hp;

    for (int t = 0; t < TT; t++) {
        __half2 pC0, pC1, pC2, pC3;
        pC0 = pC1 = pC2 = pC3 = __float2half2_rn(0.f);
        if (t + 2 < TT) {
            const __half2* gp = gb + (size_t)(t + 2) * tstride;
            pC0 = gp[0]; pC1 = gp[256]; pC2 = gp[512]; pC3 = gp[768];
        }

        unsigned long long A00 = 0, A01 = 0, A10 = 0, A11 = 0;
        unsigned long long B00 = 0, B01 = 0, B10 = 0, B11 = 0;

#pragma unroll 8
        for (int k = 0; k < KSM; k += 2) {
            {
                float2 w = Wsm[k * 256 + tid];
                ulonglong2 h = hp2[k];
                unsigned long long w0 = pk2(w.x, w.x), w1 = pk2(w.y, w.y);
                fma2_(A00, w0, h.x); fma2_(A01, w0, h.y);
                fma2_(A10, w1, h.x); fma2_(A11, w1, h.y);
            }
            {
                float2 w = Wsm[(k + 1) * 256 + tid];
                ulonglong2 h = hp2[k + 1];
                unsigned long long w0 = pk2(w.x, w.x), w1 = pk2(w.y, w.y);
                fma2_(B00, w0, h.x); fma2_(B01, w0, h.y);
                fma2_(B10, w1, h.x); fma2_(B11, w1, h.y);
            }
        }
#pragma unroll
        for (int j = 0; j < KRG; j++) {
            float2 w = wg[j];
            ulonglong2 h = hp2[KSM + j];
            unsigned long long w0 = pk2(w.x, w.x), w1 = pk2(w.y, w.y);
            if (j & 1) { fma2_(B00, w0, h.x); fma2_(B01, w0, h.y);
                         fma2_(B10, w1, h.x); fma2_(B11, w1, h.y); }
            else       { fma2_(A00, w0, h.x); fma2_(A01, w0, h.y);
                         fma2_(A10, w1, h.x); fma2_(A11, w1, h.y); }
        }

        float2 f0 = __half22float2(pA0), f1 = __half22float2(pA1);
        float2 f2 = __half22float2(pA2), f3 = __half22float2(pA3);
        pA0 = pB0; pA1 = pB1; pA2 = pB2; pA3 = pB3;
        pB0 = pC0; pB1 = pC1; pB2 = pC2; pB3 = pC3;

        ulonglong2 r0, r1;
        r0.x = add2_(add2_(A00, B00), pk2(f0.x, f1.x));
        r0.y = add2_(add2_(A01, B01), pk2(f2.x, f3.x));
        r1.x = add2_(add2_(A10, B10), pk2(f0.y, f1.y));
        r1.y = add2_(add2_(A11, B11), pk2(f2.y, f3.y));
        ((ulonglong2*)g4)[c0]     = r0;
        ((ulonglong2*)g4)[c0 + 1] = r1;
        __syncthreads();

        {
            const float2* gf2 = (const float2*)g4;
            float2 gi = gf2[(ecol      ) * 2 + erp];
            float2 gF = gf2[(ecol + 128) * 2 + erp];
            float2 gg = gf2[(ecol + 256) * 2 + erp];
            float2 go = gf2[(ecol + 384) * 2 + erp];
            cA = sig_(gF.x) * cA + sig_(gi.x) * th_(gg.x);
            cB = sig_(gF.y) * cB + sig_(gi.y) * th_(gg.y);
            float h0 = sig_(go.x) * th_(cA);
            float h1 = sig_(go.y) * th_(cB);
            hp[ecol * 2 + erp] = pk2(h0, h1);
            out[((size_t)(b0 + 2 * erp) * TT + t) * 128 + ecol] = h0;
            out[((size_t)(b0 + 2 * erp + 1) * TT + t) * 128 + ecol] = h1;
            if (t == TT - 1) {
                hn[(size_t)(b0 + 2 * erp) * 128 + ecol] = h0;
                hn[(size_t)(b0 + 2 * erp + 1) * 128 + ecol] = h1;
            }
        }
        __syncthreads();
    }
}

// ---------------------------------------------------------------------------
__global__ void transposeW3(const float* __restrict__ Whh, float* __restrict__ Wt)
{
    int i = blockIdx.x * 256 + threadIdx.x;
    if (i < 128 * 512) {
        int k = i >> 9, col = i & 511;
        Wt[i] = Whh[col * 128 + k];
    }
}

// ---------------------------------------------------------------------------
extern "C" void kernel_launch(void* const* d_in, const int* in_sizes, int n_in,
                              void* d_out, int out_size)
{
    const float* z    = (const float*)d_in[0];
    const float* Wih1 = (const float*)d_in[1];
    const float* Whh1 = (const float*)d_in[2];
    const float* bih1 = (const float*)d_in[3];
    const float* bhh1 = (const float*)d_in[4];
    const float* Wih2 = (const float*)d_in[5];
    const float* Whh2 = (const float*)d_in[6];
    const float* bih2 = (const float*)d_in[7];
    const float* bhh2 = (const float*)d_in[8];
    const float* Wih3 = (const float*)d_in[9];
    const float* Whh3 = (const float*)d_in[10];
    const float* bih3 = (const float*)d_in[11];
    const float* bhh3 = (const float*)d_in[12];

    float* dec = (float*)d_out;                        // [B,T,128]
    float* hn  = dec + (size_t)BB * TT * 128;          // [1,B,128]

    __half *gx, *h1, *h2;
    float* Wt3;
    cudaGetSymbolAddress((void**)&gx, g_gxh);
    cudaGetSymbolAddress((void**)&h1, g_h1);
    cudaGetSymbolAddress((void**)&h2, g_h2);
    cudaGetSymbolAddress((void**)&Wt3, g_Wt3);

    cudaFuncSetAttribute(lstm_recur_big,
                         cudaFuncAttributeMaxDynamicSharedMemorySize, SMEM_BIG);

    transposeW3<<<256, 256>>>(Whh3, Wt3);

    // Layer 1: 64 -> 32   (x fp32)
    lstm_projM<64, 128, true><<<2048, 256>>>(z, Wih1, bih1, bhh1, gx);
    lstm_recur_small<32><<<BB / 2, 128>>>(gx, Whh1, h1);

    // Layer 2: 32 -> 48   (x fp16)
    lstm_projM<32, 192, false><<<2048, 256>>>(h1, Wih2, bih2, bhh2, gx);
    lstm_recur_small<48><<<BB / 2, 192>>>(gx, Whh2, h2);

    // Layer 3: 48 -> 128  (x fp16)
    lstm_projM<48, 512, false><<<2048, 256>>>(h2, Wih3, bih3, bhh3, gx);
    lstm_recur_big<<<BB / 4, 256, SMEM_BIG>>>(gx, Wt3, dec, hn);
}

// round 13
// speedup vs baseline: 1.6364x; 1.6364x over previous
#include <cuda_runtime.h>
#include <cuda_fp16.h>
#include <math.h>

#define BB 512
#define TT 512

// ---------------- device scratch (allocation-free rule) ----------------
__device__ __half g_gxh[(size_t)TT * BB * 512];   // gate pre-activations (fp16)
__device__ float  g_h1[(size_t)BB * TT * 32];     // layer1 output
__device__ float  g_h2[(size_t)BB * TT * 48];     // layer2 output
__device__ float  g_Wt3[128 * 512];               // Whh3 transposed [k][col]

// ---------------- f32x2 helpers ----------------
__device__ __forceinline__ unsigned long long pk2(float a, float b) {
    unsigned long long r;
    asm("mov.b64 %0, {%1,%2};" : "=l"(r) : "f"(a), "f"(b));
    return r;
}
__device__ __forceinline__ void fma2_(unsigned long long& d, unsigned long long a,
                                      unsigned long long b) {
    asm("fma.rn.f32x2 %0, %1, %2, %0;" : "+l"(d) : "l"(a), "l"(b));
}
__device__ __forceinline__ unsigned long long add2_(unsigned long long a,
                                                    unsigned long long b) {
    unsigned long long r;
    asm("add.rn.f32x2 %0, %1, %2;" : "=l"(r) : "l"(a), "l"(b));
    return r;
}
__device__ __forceinline__ float sig_(float x) { return 1.0f / (1.0f + __expf(-x)); }
__device__ __forceinline__ float th_(float x) { return 1.0f - 2.0f / (__expf(2.0f * x) + 1.0f); }

// ---------------- mma helpers (verified R8/R10) ----------------
__device__ __forceinline__ unsigned smem_u32(const void* p) {
    return (unsigned)__cvta_generic_to_shared(p);
}
__device__ __forceinline__ void ldmx4(unsigned& a0, unsigned& a1, unsigned& a2,
                                      unsigned& a3, unsigned addr) {
    asm volatile("ldmatrix.sync.aligned.m8n8.x4.shared.b16 {%0,%1,%2,%3}, [%4];"
                 : "=r"(a0), "=r"(a1), "=r"(a2), "=r"(a3) : "r"(addr));
}
__device__ __forceinline__ void mma16816(float* d, unsigned a0, unsigned a1,
                                         unsigned a2, unsigned a3,
                                         unsigned b0, unsigned b1) {
    asm volatile(
        "mma.sync.aligned.m16n8k16.row.col.f32.f16.f16.f32 "
        "{%0,%1,%2,%3}, {%4,%5,%6,%7}, {%8,%9}, {%0,%1,%2,%3};"
        : "+f"(d[0]), "+f"(d[1]), "+f"(d[2]), "+f"(d[3])
        : "r"(a0), "r"(a1), "r"(a2), "r"(a3), "r"(b0), "r"(b1));
}

// ---------------------------------------------------------------------------
// Input projection via tensor cores, COALESCED stores: mma fragments are
// staged in padded smem (row stride N+8 halves -> store banks 4*lq+l4 all
// distinct, conflict-free), then full rows streamed to gmem as float4.
// 256 threads (8 warps), 32 rows/tile; warp owns N/8 gate cols.
// ---------------------------------------------------------------------------
template <int D, int N>
__global__ void __launch_bounds__(256)
lstm_projM(const float* __restrict__ xin, const float* __restrict__ Wih,
           const float* __restrict__ bih, const float* __restrict__ bhh,
           __half* __restrict__ gx)
{
    constexpr int KT = D / 16;        // k-tiles
    constexpr int NTILES = N / 64;    // n-tiles of 8 per warp (8 warps)
    constexpr int NCW = N / 8;        // cols per warp
    constexpr int XPAD = D + 8;
    constexpr int OPAD = N + 8;

    __shared__ __align__(16) __half xs[32][XPAD];
    __shared__ __align__(16) __half os[32][OPAD];

    const int tid = threadIdx.x;
    const int w = tid >> 5, l = tid & 31;
    const int l4 = l & 3, lq = l >> 2;
    const int wbase = w * NCW;

    // B fragments from Wih [N][D] row-major (col-major [DxN] for row.col mma)
    unsigned bf[KT][NTILES][2];
#pragma unroll
    for (int kt = 0; kt < KT; kt++)
#pragma unroll
        for (int ti = 0; ti < NTILES; ti++) {
            int n = wbase + ti * 8 + lq;
            int k0 = kt * 16 + 2 * l4;
            __half2 v0 = __floats2half2_rn(__ldg(&Wih[n * D + k0]),
                                           __ldg(&Wih[n * D + k0 + 1]));
            __half2 v1 = __floats2half2_rn(__ldg(&Wih[n * D + k0 + 8]),
                                           __ldg(&Wih[n * D + k0 + 9]));
            bf[kt][ti][0] = *(unsigned*)&v0;
            bf[kt][ti][1] = *(unsigned*)&v1;
        }
    float2 b2[NTILES];
#pragma unroll
    for (int ti = 0; ti < NTILES; ti++) {
        int n0 = wbase + ti * 8 + 2 * l4;
        b2[ti] = make_float2(__ldg(&bih[n0]) + __ldg(&bhh[n0]),
                             __ldg(&bih[n0 + 1]) + __ldg(&bhh[n0 + 1]));
    }

    const int arow = l & 15, acg = (l >> 4) * 8;
    const int ntiles_tot = (BB * TT) / 32;

#pragma unroll 1
    for (int tile = blockIdx.x; tile < ntiles_tot; tile += gridDim.x) {
        __syncthreads();   // protect xs/os reads of previous iter
#pragma unroll 1
        for (int i = tid; i < 32 * (D / 4); i += 256) {
            int row = i / (D / 4), k4 = i % (D / 4);
            float4 v = ((const float4*)(xin + (size_t)(tile * 32 + row) * D))[k4];
            *(__half2*)&xs[row][4 * k4]     = __floats2half2_rn(v.x, v.y);
            *(__half2*)&xs[row][4 * k4 + 2] = __floats2half2_rn(v.z, v.w);
        }
        __syncthreads();

#pragma unroll
        for (int mt = 0; mt < 2; mt++) {
            unsigned aa[KT][4];
#pragma unroll
            for (int kt = 0; kt < KT; kt++)
                ldmx4(aa[kt][0], aa[kt][1], aa[kt][2], aa[kt][3],
                      smem_u32(&xs[mt * 16 + arow][acg + 16 * kt]));

            float d[NTILES][4];
#pragma unroll
            for (int ti = 0; ti < NTILES; ti++) {
                d[ti][0] = b2[ti].x; d[ti][1] = b2[ti].y;
                d[ti][2] = b2[ti].x; d[ti][3] = b2[ti].y;
            }
#pragma unroll
            for (int kt = 0; kt < KT; kt++)
#pragma unroll
                for (int ti = 0; ti < NTILES; ti++)
                    mma16816(d[ti], aa[kt][0], aa[kt][1], aa[kt][2], aa[kt][3],
                             bf[kt][ti][0], bf[kt][ti][1]);

            // stage to smem (conflict-free: banks 4*lq + l4 distinct)
#pragma unroll
            for (int ti = 0; ti < NTILES; ti++)
#pragma unroll
                for (int rr = 0; rr < 2; rr++)
                    *(__half2*)&os[mt * 16 + lq + 8 * rr][wbase + ti * 8 + 2 * l4] =
                        __floats2half2_rn(d[ti][2 * rr], d[ti][2 * rr + 1]);
        }
        __syncthreads();

        // coalesced row stream-out: row m -> (t = m & 511, b = m >> 9)
#pragma unroll 1
        for (int i = tid; i < 32 * (N / 8); i += 256) {
            int row = i / (N / 8), c8 = i % (N / 8);
            int m = tile * 32 + row;
            int b = m >> 9, t = m & 511;
            *(float4*)(gx + ((size_t)t * BB + b) * N + 8 * c8) =
                *(const float4*)&os[row][8 * c8];
        }
    }
}

// ---------------------------------------------------------------------------
// Small-layer recurrence (R4-proven), fp16 gx, depth-2 prefetch, fp32 out.
// ---------------------------------------------------------------------------
template <int H>
__global__ void __launch_bounds__(4 * H)
lstm_recur_small(const __half* __restrict__ gx,  // [T][B][4H] fp16
                 const float* __restrict__ Whh,  // [4H][H]
                 float* __restrict__ out)        // [B][T][H]
{
    constexpr int G = 4 * H;
    const int col = threadIdx.x;
    const int b0 = blockIdx.x * 2;

    unsigned long long wh2[H];
#pragma unroll
    for (int k = 0; k < H; k++) {
        float w = __ldg(&Whh[col * H + k]);
        wh2[k] = pk2(w, w);
    }

    __shared__ unsigned long long h2[H];
    __shared__ unsigned long long g2[G];
    if (col < H) h2[col] = 0ull;

    const int erow = col & 1, ecol = col >> 1;
    float c = 0.f;

    const __half* gbase = gx + (size_t)b0 * G + col;
    const size_t tstride = (size_t)BB * G;

    __half A0 = gbase[0], A1 = gbase[G];
    __half B0 = gbase[tstride], B1 = gbase[tstride + G];
    __syncthreads();

    for (int t = 0; t < TT; t++) {
        __half C0 = __float2half(0.f), C1 = C0;
        if (t + 2 < TT) {
            const __half* gp = gbase + (size_t)(t + 2) * tstride;
            C0 = gp[0]; C1 = gp[G];
        }
        unsigned long long a0 = 0ull, a1 = 0ull, a2 = 0ull, a3 = 0ull;
#pragma unroll
        for (int k = 0; k < H; k += 4) {
            fma2_(a0, wh2[k + 0], h2[k + 0]);
            fma2_(a1, wh2[k + 1], h2[k + 1]);
            fma2_(a2, wh2[k + 2], h2[k + 2]);
            fma2_(a3, wh2[k + 3], h2[k + 3]);
        }
        g2[col] = add2_(add2_(add2_(a0, a1), add2_(a2, a3)),
                        pk2(__half2float(A0), __half2float(A1)));
        A0 = B0; A1 = B1; B0 = C0; B1 = C1;
        __syncthreads();

        if (col < 2 * H) {
            const float* gf = (const float*)g2;
            float gi = gf[2 * ecol + erow];
            float gF = gf[2 * (H + ecol) + erow];
            float gg = gf[2 * (2 * H + ecol) + erow];
            float go = gf[2 * (3 * H + ecol) + erow];
            c = sig_(gF) * c + sig_(gi) * th_(gg);
            float h = sig_(go) * th_(c);
            ((float*)h2)[2 * ecol + erow] = h;
            out[((size_t)(b0 + erow) * TT + t) * H + ecol] = h;
        }
        __syncthreads();
    }
}

// ---------------------------------------------------------------------------
// Layer-3 recurrence (R4-proven): KSM=96 k-rows in smem, 32 in registers.
// ---------------------------------------------------------------------------
#define KSM 96
#define KRG (128 - KSM)
#define SMEM_BIG (KSM * 512 * 4 + 128 * 16 + 512 * 16)   // 206,848 B

__global__ void __launch_bounds__(256)
lstm_recur_big(const __half* __restrict__ gx,  // [T][B][512] fp16
               const float* __restrict__ Wt,   // [128][512] transposed Whh3
               float* __restrict__ out,        // [B][T][128]
               float* __restrict__ hn)         // [B][128]
{
    extern __shared__ char sraw[];
    float2* Wsm = (float2*)sraw;                                         // [KSM][256]
    unsigned long long* hp = (unsigned long long*)(sraw + KSM * 512 * 4);        // [128][2]
    unsigned long long* g4 = (unsigned long long*)(sraw + KSM * 512 * 4 + 2048); // [512][2]

    const int tid = threadIdx.x;
    const int b0 = blockIdx.x * 4;
    const int c0 = tid * 2;

    for (int i = tid; i < KSM * 128; i += 256)
        ((float4*)Wsm)[i] = ((const float4*)Wt)[i];
    float2 wg[KRG];
#pragma unroll
    for (int j = 0; j < KRG; j++)
        wg[j] = *(const float2*)(Wt + (size_t)(KSM + j) * 512 + c0);

    hp[tid] = 0ull;

    const int ecol = tid & 127, erp = tid >> 7;
    float cA = 0.f, cB = 0.f;

    const __half2* gb = (const __half2*)(gx + (size_t)b0 * 512 + c0);
    const size_t tstride = (size_t)BB * 256;   // in half2 units

    __half2 pA0 = gb[0], pA1 = gb[256], pA2 = gb[512], pA3 = gb[768];
    __half2 pB0 = gb[tstride + 0], pB1 = gb[tstride + 256],
            pB2 = gb[tstride + 512], pB3 = gb[tstride + 768];
    __syncthreads();

    const ulonglong2* hp2 = (const ulonglong2*)hp;

    for (int t = 0; t < TT; t++) {
        __half2 pC0, pC1, pC2, pC3;
        pC0 = pC1 = pC2 = pC3 = __float2half2_rn(0.f);
        if (t + 2 < TT) {
            const __half2* gp = gb + (size_t)(t + 2) * tstride;
            pC0 = gp[0]; pC1 = gp[256]; pC2 = gp[512]; pC3 = gp[768];
        }

        unsigned long long A00 = 0, A01 = 0, A10 = 0, A11 = 0;
        unsigned long long B00 = 0, B01 = 0, B10 = 0, B11 = 0;

#pragma unroll 8
        for (int k = 0; k < KSM; k += 2) {
            {
                float2 w = Wsm[k * 256 + tid];
                ulonglong2 h = hp2[k];
                unsigned long long w0 = pk2(w.x, w.x), w1 = pk2(w.y, w.y);
                fma2_(A00, w0, h.x); fma2_(A01, w0, h.y);
                fma2_(A10, w1, h.x); fma2_(A11, w1, h.y);
            }
            {
                float2 w = Wsm[(k + 1) * 256 + tid];
                ulonglong2 h = hp2[k + 1];
                unsigned long long w0 = pk2(w.x, w.x), w1 = pk2(w.y, w.y);
                fma2_(B00, w0, h.x); fma2_(B01, w0, h.y);
                fma2_(B10, w1, h.x); fma2_(B11, w1, h.y);
            }
        }
#pragma unroll
        for (int j = 0; j < KRG; j++) {
            float2 w = wg[j];
            ulonglong2 h = hp2[KSM + j];
            unsigned long long w0 = pk2(w.x, w.x), w1 = pk2(w.y, w.y);
            if (j & 1) { fma2_(B00, w0, h.x); fma2_(B01, w0, h.y);
                         fma2_(B10, w1, h.x); fma2_(B11, w1, h.y); }
            else       { fma2_(A00, w0, h.x); fma2_(A01, w0, h.y);
                         fma2_(A10, w1, h.x); fma2_(A11, w1, h.y); }
        }

        float2 f0 = __half22float2(pA0), f1 = __half22float2(pA1);
        float2 f2 = __half22float2(pA2), f3 = __half22float2(pA3);
        pA0 = pB0; pA1 = pB1; pA2 = pB2; pA3 = pB3;
        pB0 = pC0; pB1 = pC1; pB2 = pC2; pB3 = pC3;

        ulonglong2 r0, r1;
        r0.x = add2_(add2_(A00, B00), pk2(f0.x, f1.x));
        r0.y = add2_(add2_(A01, B01), pk2(f2.x, f3.x));
        r1.x = add2_(add2_(A10, B10), pk2(f0.y, f1.y));
        r1.y = add2_(add2_(A11, B11), pk2(f2.y, f3.y));
        ((ulonglong2*)g4)[c0]     = r0;
        ((ulonglong2*)g4)[c0 + 1] = r1;
        __syncthreads();

        {
            const float2* gf2 = (const float2*)g4;
            float2 gi = gf2[(ecol      ) * 2 + erp];
            float2 gF = gf2[(ecol + 128) * 2 + erp];
            float2 gg = gf2[(ecol + 256) * 2 + erp];
            float2 go = gf2[(ecol + 384) * 2 + erp];
            cA = sig_(gF.x) * cA + sig_(gi.x) * th_(gg.x);
            cB = sig_(gF.y) * cB + sig_(gi.y) * th_(gg.y);
            float h0 = sig_(go.x) * th_(cA);
            float h1 = sig_(go.y) * th_(cB);
            hp[ecol * 2 + erp] = pk2(h0, h1);
            out[((size_t)(b0 + 2 * erp) * TT + t) * 128 + ecol] = h0;
            out[((size_t)(b0 + 2 * erp + 1) * TT + t) * 128 + ecol] = h1;
            if (t == TT - 1) {
                hn[(size_t)(b0 + 2 * erp) * 128 + ecol] = h0;
                hn[(size_t)(b0 + 2 * erp + 1) * 128 + ecol] = h1;
            }
        }
        __syncthreads();
    }
}

// ---------------------------------------------------------------------------
__global__ void transposeW3(const float* __restrict__ Whh, float* __restrict__ Wt)
{
    int i = blockIdx.x * 256 + threadIdx.x;
    if (i < 128 * 512) {
        int k = i >> 9, col = i & 511;
        Wt[i] = Whh[col * 128 + k];
    }
}

// ---------------------------------------------------------------------------
extern "C" void kernel_launch(void* const* d_in, const int* in_sizes, int n_in,
                              void* d_out, int out_size)
{
    const float* z    = (const float*)d_in[0];
    const float* Wih1 = (const float*)d_in[1];
    const float* Whh1 = (const float*)d_in[2];
    const float* bih1 = (const float*)d_in[3];
    const float* bhh1 = (const float*)d_in[4];
    const float* Wih2 = (const float*)d_in[5];
    const float* Whh2 = (const float*)d_in[6];
    const float* bih2 = (const float*)d_in[7];
    const float* bhh2 = (const float*)d_in[8];
    const float* Wih3 = (const float*)d_in[9];
    const float* Whh3 = (const float*)d_in[10];
    const float* bih3 = (const float*)d_in[11];
    const float* bhh3 = (const float*)d_in[12];

    float* dec = (float*)d_out;                        // [B,T,128]
    float* hn  = dec + (size_t)BB * TT * 128;          // [1,B,128]

    __half* gx;
    float *h1, *h2, *Wt3;
    cudaGetSymbolAddress((void**)&gx, g_gxh);
    cudaGetSymbolAddress((void**)&h1, g_h1);
    cudaGetSymbolAddress((void**)&h2, g_h2);
    cudaGetSymbolAddress((void**)&Wt3, g_Wt3);

    cudaFuncSetAttribute(lstm_recur_big,
                         cudaFuncAttributeMaxDynamicSharedMemorySize, SMEM_BIG);

    transposeW3<<<256, 256>>>(Whh3, Wt3);

    // Layer 1: 64 -> 32
    lstm_projM<64, 128><<<2048, 256>>>(z, Wih1, bih1, bhh1, gx);
    lstm_recur_small<32><<<BB / 2, 128>>>(gx, Whh1, h1);

    // Layer 2: 32 -> 48
    lstm_projM<32, 192><<<2048, 256>>>(h1, Wih2, bih2, bhh2, gx);
    lstm_recur_small<48><<<BB / 2, 192>>>(gx, Whh2, h2);

    // Layer 3: 48 -> 128
    lstm_projM<48, 512><<<2048, 256>>>(h2, Wih3, bih3, bhh3, gx);
    lstm_recur_big<<<BB / 4, 256, SMEM_BIG>>>(gx, Wt3, dec, hn);
}

// round 14
// speedup vs baseline: 1.7621x; 1.0768x over previous
#include <cuda_runtime.h>
#include <cuda_fp16.h>
#include <math.h>

#define BB 512
#define TT 512

// ---------------- device scratch (allocation-free rule) ----------------
__device__ __half g_gxh[(size_t)TT * BB * 512];   // gate pre-activations (fp16)
__device__ float  g_h1[(size_t)BB * TT * 32];     // layer1 output
__device__ float  g_h2[(size_t)BB * TT * 48];     // layer2 output
__device__ float  g_Wt3[128 * 512];               // Whh3 transposed [k][col]

// ---------------- f32x2 helpers ----------------
__device__ __forceinline__ unsigned long long pk2(float a, float b) {
    unsigned long long r;
    asm("mov.b64 %0, {%1,%2};" : "=l"(r) : "f"(a), "f"(b));
    return r;
}
__device__ __forceinline__ void fma2_(unsigned long long& d, unsigned long long a,
                                      unsigned long long b) {
    asm("fma.rn.f32x2 %0, %1, %2, %0;" : "+l"(d) : "l"(a), "l"(b));
}
__device__ __forceinline__ unsigned long long add2_(unsigned long long a,
                                                    unsigned long long b) {
    unsigned long long r;
    asm("add.rn.f32x2 %0, %1, %2;" : "=l"(r) : "l"(a), "l"(b));
    return r;
}
__device__ __forceinline__ float sig_(float x) { return 1.0f / (1.0f + __expf(-x)); }
__device__ __forceinline__ float th_(float x) { return 1.0f - 2.0f / (__expf(2.0f * x) + 1.0f); }

// ---------------- mma helpers (verified R8/R13) ----------------
__device__ __forceinline__ unsigned smem_u32(const void* p) {
    return (unsigned)__cvta_generic_to_shared(p);
}
__device__ __forceinline__ void ldmx4(unsigned& a0, unsigned& a1, unsigned& a2,
                                      unsigned& a3, unsigned addr) {
    asm volatile("ldmatrix.sync.aligned.m8n8.x4.shared.b16 {%0,%1,%2,%3}, [%4];"
                 : "=r"(a0), "=r"(a1), "=r"(a2), "=r"(a3) : "r"(addr));
}
__device__ __forceinline__ void mma16816(float* d, unsigned a0, unsigned a1,
                                         unsigned a2, unsigned a3,
                                         unsigned b0, unsigned b1) {
    asm volatile(
        "mma.sync.aligned.m16n8k16.row.col.f32.f16.f16.f32 "
        "{%0,%1,%2,%3}, {%4,%5,%6,%7}, {%8,%9}, {%0,%1,%2,%3};"
        : "+f"(d[0]), "+f"(d[1]), "+f"(d[2]), "+f"(d[3])
        : "r"(a0), "r"(a1), "r"(a2), "r"(a3), "r"(b0), "r"(b1));
}

// ---------------------------------------------------------------------------
// Input projection via tensor cores, coalesced stores (R13-proven WIN).
// ---------------------------------------------------------------------------
template <int D, int N>
__global__ void __launch_bounds__(256)
lstm_projM(const float* __restrict__ xin, const float* __restrict__ Wih,
           const float* __restrict__ bih, const float* __restrict__ bhh,
           __half* __restrict__ gx)
{
    constexpr int KT = D / 16;
    constexpr int NTILES = N / 64;
    constexpr int NCW = N / 8;
    constexpr int XPAD = D + 8;
    constexpr int OPAD = N + 8;

    __shared__ __align__(16) __half xs[32][XPAD];
    __shared__ __align__(16) __half os[32][OPAD];

    const int tid = threadIdx.x;
    const int w = tid >> 5, l = tid & 31;
    const int l4 = l & 3, lq = l >> 2;
    const int wbase = w * NCW;

    unsigned bf[KT][NTILES][2];
#pragma unroll
    for (int kt = 0; kt < KT; kt++)
#pragma unroll
        for (int ti = 0; ti < NTILES; ti++) {
            int n = wbase + ti * 8 + lq;
            int k0 = kt * 16 + 2 * l4;
            __half2 v0 = __floats2half2_rn(__ldg(&Wih[n * D + k0]),
                                           __ldg(&Wih[n * D + k0 + 1]));
            __half2 v1 = __floats2half2_rn(__ldg(&Wih[n * D + k0 + 8]),
                                           __ldg(&Wih[n * D + k0 + 9]));
            bf[kt][ti][0] = *(unsigned*)&v0;
            bf[kt][ti][1] = *(unsigned*)&v1;
        }
    float2 b2[NTILES];
#pragma unroll
    for (int ti = 0; ti < NTILES; ti++) {
        int n0 = wbase + ti * 8 + 2 * l4;
        b2[ti] = make_float2(__ldg(&bih[n0]) + __ldg(&bhh[n0]),
                             __ldg(&bih[n0 + 1]) + __ldg(&bhh[n0 + 1]));
    }

    const int arow = l & 15, acg = (l >> 4) * 8;
    const int ntiles_tot = (BB * TT) / 32;

#pragma unroll 1
    for (int tile = blockIdx.x; tile < ntiles_tot; tile += gridDim.x) {
        __syncthreads();
#pragma unroll 1
        for (int i = tid; i < 32 * (D / 4); i += 256) {
            int row = i / (D / 4), k4 = i % (D / 4);
            float4 v = ((const float4*)(xin + (size_t)(tile * 32 + row) * D))[k4];
            *(__half2*)&xs[row][4 * k4]     = __floats2half2_rn(v.x, v.y);
            *(__half2*)&xs[row][4 * k4 + 2] = __floats2half2_rn(v.z, v.w);
        }
        __syncthreads();

#pragma unroll
        for (int mt = 0; mt < 2; mt++) {
            unsigned aa[KT][4];
#pragma unroll
            for (int kt = 0; kt < KT; kt++)
                ldmx4(aa[kt][0], aa[kt][1], aa[kt][2], aa[kt][3],
                      smem_u32(&xs[mt * 16 + arow][acg + 16 * kt]));

            float d[NTILES][4];
#pragma unroll
            for (int ti = 0; ti < NTILES; ti++) {
                d[ti][0] = b2[ti].x; d[ti][1] = b2[ti].y;
                d[ti][2] = b2[ti].x; d[ti][3] = b2[ti].y;
            }
#pragma unroll
            for (int kt = 0; kt < KT; kt++)
#pragma unroll
                for (int ti = 0; ti < NTILES; ti++)
                    mma16816(d[ti], aa[kt][0], aa[kt][1], aa[kt][2], aa[kt][3],
                             bf[kt][ti][0], bf[kt][ti][1]);

#pragma unroll
            for (int ti = 0; ti < NTILES; ti++)
#pragma unroll
                for (int rr = 0; rr < 2; rr++)
                    *(__half2*)&os[mt * 16 + lq + 8 * rr][wbase + ti * 8 + 2 * l4] =
                        __floats2half2_rn(d[ti][2 * rr], d[ti][2 * rr + 1]);
        }
        __syncthreads();

#pragma unroll 1
        for (int i = tid; i < 32 * (N / 8); i += 256) {
            int row = i / (N / 8), c8 = i % (N / 8);
            int m = tile * 32 + row;
            int b = m >> 9, t = m & 511;
            *(float4*)(gx + ((size_t)t * BB + b) * N + 8 * c8) =
                *(const float4*)&os[row][8 * c8];
        }
    }
}

// ---------------------------------------------------------------------------
// Small-layer recurrence, Bc=4 batch rows per block (128 blocks = 1 wave).
// Thread = gate col; epilogue: thread tid -> cell (hcol = tid>>2, r = tid&3).
// ---------------------------------------------------------------------------
template <int H>
__global__ void __launch_bounds__(4 * H)
lstm_recur_small(const __half* __restrict__ gx,  // [T][B][4H] fp16
                 const float* __restrict__ Whh,  // [4H][H]
                 float* __restrict__ out)        // [B][T][H]
{
    constexpr int G = 4 * H;
    const int col = threadIdx.x;
    const int b0 = blockIdx.x * 4;

    unsigned long long wh2[H];
#pragma unroll
    for (int k = 0; k < H; k++) {
        float w = __ldg(&Whh[col * H + k]);
        wh2[k] = pk2(w, w);
    }

    __shared__ __align__(16) unsigned long long h2[H][2];  // [hcol][rp], rows (2rp,2rp+1)
    __shared__ __align__(16) unsigned long long g2[G][2];  // [gatecol][rp]
    ((float*)h2)[col] = 0.f;      // 4H floats == 4H threads

    const int hcol = col >> 2, er = col & 3;
    const int erp = er >> 1, elane = er & 1;
    float c = 0.f;

    const __half* gbase = gx + (size_t)b0 * G + col;
    const size_t ts = (size_t)BB * G;

    __half A0 = gbase[0], A1 = gbase[G], A2 = gbase[2 * G], A3 = gbase[3 * G];
    __half B0 = gbase[ts], B1 = gbase[ts + G], B2 = gbase[ts + 2 * G], B3 = gbase[ts + 3 * G];
    __syncthreads();

    const ulonglong2* hp2 = (const ulonglong2*)h2;

    for (int t = 0; t < TT; t++) {
        __half C0 = __float2half(0.f), C1 = C0, C2 = C0, C3 = C0;
        if (t + 2 < TT) {
            const __half* gp = gbase + (size_t)(t + 2) * ts;
            C0 = gp[0]; C1 = gp[G]; C2 = gp[2 * G]; C3 = gp[3 * G];
        }
        unsigned long long a00 = 0, a01 = 0, a10 = 0, a11 = 0;
#pragma unroll
        for (int k = 0; k < H; k += 2) {
            ulonglong2 ha = hp2[k];
            ulonglong2 hb = hp2[k + 1];
            fma2_(a00, wh2[k], ha.x);     fma2_(a01, wh2[k], ha.y);
            fma2_(a10, wh2[k + 1], hb.x); fma2_(a11, wh2[k + 1], hb.y);
        }
        ulonglong2 s;
        s.x = add2_(add2_(a00, a10), pk2(__half2float(A0), __half2float(A1)));
        s.y = add2_(add2_(a01, a11), pk2(__half2float(A2), __half2float(A3)));
        ((ulonglong2*)g2)[col] = s;
        A0 = B0; A1 = B1; A2 = B2; A3 = B3;
        B0 = C0; B1 = C1; B2 = C2; B3 = C3;
        __syncthreads();

        {
            const float* gf = (const float*)g2;   // float idx = 4*g + 2*rp + lane
            int base = 4 * hcol + 2 * erp + elane;
            float gi = gf[base];
            float gF = gf[base + 4 * H];
            float gg = gf[base + 8 * H];
            float go = gf[base + 12 * H];
            c = sig_(gF) * c + sig_(gi) * th_(gg);
            float h = sig_(go) * th_(c);
            ((float*)h2)[base] = h;               // base == 4*hcol+2*erp+elane
            out[((size_t)(b0 + er) * TT + t) * H + hcol] = h;
        }
        __syncthreads();
    }
}

// ---------------------------------------------------------------------------
// Layer-3 recurrence, k-split over 512 threads (16 warps):
//  khalf0: k in [0,32) from smem + [32,64) from regs
//  khalf1: k in [64,96) from smem + [96,128) from regs (+ gx prefetch)
// Wsm holds only 64 k-rows (crossbar traffic halved); partials combined in
// epilogue (reads g4a+g4b). 1 cell per thread. 2 syncs/step.
// ---------------------------------------------------------------------------
#define RB_KREG 32
#define SMEM_BIG (64 * 512 * 4 + 256 * 8 + 512 * 16 + 512 * 16)   // 149,504 B

__global__ void __launch_bounds__(512, 1)
lstm_recur_big(const __half* __restrict__ gx,  // [T][B][512] fp16
               const float* __restrict__ Wt,   // [128][512] transposed Whh3
               float* __restrict__ out,        // [B][T][128]
               float* __restrict__ hn)         // [B][128]
{
    extern __shared__ char sraw[];
    float2* Wsm = (float2*)sraw;                                          // [64][256] float2
    unsigned long long* hp  = (unsigned long long*)(sraw + 131072);        // [128][2]
    unsigned long long* g4a = (unsigned long long*)(sraw + 131072 + 2048); // [512][2]
    unsigned long long* g4b = (unsigned long long*)(sraw + 131072 + 2048 + 8192);

    const int tid = threadIdx.x;
    const int khalf = tid >> 8;        // 0 or 1
    const int stid = tid & 255;
    const int c0 = stid * 2;           // gate col pair
    const int b0 = blockIdx.x * 4;

    // Wsm rows 0-31 = Wt rows 0-31; rows 32-63 = Wt rows 64-95
    for (int i = tid; i < 64 * 128; i += 512) {
        int row = i >> 7;
        int src = row < 32 ? row : row + 32;
        ((float4*)Wsm)[i] = ((const float4*)Wt)[(size_t)src * 128 + (i & 127)];
    }
    // register tail: khalf0 -> Wt rows [32,64); khalf1 -> Wt rows [96,128)
    const int tail0 = khalf ? 96 : 32;
    float2 wg[RB_KREG];
#pragma unroll
    for (int j = 0; j < RB_KREG; j++)
        wg[j] = *(const float2*)(Wt + (size_t)(tail0 + j) * 512 + c0);

    if (tid < 256) hp[tid] = 0ull;

    // epilogue mapping: 1 cell per thread
    const int ecol = tid & 127, er = tid >> 7;      // er in 0..3
    const int erp = er >> 1, elane = er & 1;
    float c = 0.f;

    // gx prefetch (khalf1 only)
    const __half2* gb = (const __half2*)(gx + (size_t)b0 * 512) + stid;
    const size_t ts2 = (size_t)BB * 256;   // half2 stride per t
    __half2 pA0, pA1, pA2, pA3, pB0, pB1, pB2, pB3;
    if (khalf) {
        pA0 = gb[0]; pA1 = gb[256]; pA2 = gb[512]; pA3 = gb[768];
        pB0 = gb[ts2 + 0]; pB1 = gb[ts2 + 256]; pB2 = gb[ts2 + 512]; pB3 = gb[ts2 + 768];
    }
    __syncthreads();

    const ulonglong2* hp2 = (const ulonglong2*)hp;
    const int srow0 = khalf ? 32 : 0;     // smem W row base
    const int ksm_h = khalf ? 64 : 0;     // h index base for smem part
    const int krg_h = khalf ? 96 : 32;    // h index base for reg part

    for (int t = 0; t < TT; t++) {
        __half2 pC0, pC1, pC2, pC3;
        if (khalf) {
            pC0 = pC1 = pC2 = pC3 = __float2half2_rn(0.f);
            if (t + 2 < TT) {
                const __half2* gp = gb + (size_t)(t + 2) * ts2;
                pC0 = gp[0]; pC1 = gp[256]; pC2 = gp[512]; pC3 = gp[768];
            }
        }

        unsigned long long A00 = 0, A01 = 0, A10 = 0, A11 = 0;
        unsigned long long B00 = 0, B01 = 0, B10 = 0, B11 = 0;

#pragma unroll 8
        for (int i = 0; i < 32; i++) {
            float2 w = Wsm[(srow0 + i) * 256 + stid];
            ulonglong2 h = hp2[ksm_h + i];
            unsigned long long w0 = pk2(w.x, w.x), w1 = pk2(w.y, w.y);
            if (i & 1) { fma2_(B00, w0, h.x); fma2_(B01, w0, h.y);
                         fma2_(B10, w1, h.x); fma2_(B11, w1, h.y); }
            else       { fma2_(A00, w0, h.x); fma2_(A01, w0, h.y);
                         fma2_(A10, w1, h.x); fma2_(A11, w1, h.y); }
        }
#pragma unroll
        for (int j = 0; j < RB_KREG; j++) {
            float2 w = wg[j];
            ulonglong2 h = hp2[krg_h + j];
            unsigned long long w0 = pk2(w.x, w.x), w1 = pk2(w.y, w.y);
            if (j & 1) { fma2_(B00, w0, h.x); fma2_(B01, w0, h.y);
                         fma2_(B10, w1, h.x); fma2_(B11, w1, h.y); }
            else       { fma2_(A00, w0, h.x); fma2_(A01, w0, h.y);
                         fma2_(A10, w1, h.x); fma2_(A11, w1, h.y); }
        }

        ulonglong2 r0, r1;
        if (khalf) {
            float2 f0 = __half22float2(pA0), f1 = __half22float2(pA1);
            float2 f2 = __half22float2(pA2), f3 = __half22float2(pA3);
            pA0 = pB0; pA1 = pB1; pA2 = pB2; pA3 = pB3;
            pB0 = pC0; pB1 = pC1; pB2 = pC2; pB3 = pC3;
            r0.x = add2_(add2_(A00, B00), pk2(f0.x, f1.x));
            r0.y = add2_(add2_(A01, B01), pk2(f2.x, f3.x));
            r1.x = add2_(add2_(A10, B10), pk2(f0.y, f1.y));
            r1.y = add2_(add2_(A11, B11), pk2(f2.y, f3.y));
            ((ulonglong2*)g4b)[c0]     = r0;
            ((ulonglong2*)g4b)[c0 + 1] = r1;
        } else {
            r0.x = add2_(A00, B00);
            r0.y = add2_(A01, B01);
            r1.x = add2_(A10, B10);
            r1.y = add2_(A11, B11);
            ((ulonglong2*)g4a)[c0]     = r0;
            ((ulonglong2*)g4a)[c0 + 1] = r1;
        }
        __syncthreads();

        {
            const float* fa = (const float*)g4a;  // float idx = 4*g + 2*rp + lane
            const float* fb = (const float*)g4b;
            int base = 4 * ecol + 2 * erp + elane;
            float gi = fa[base]        + fb[base];
            float gF = fa[base + 512]  + fb[base + 512];
            float gg = fa[base + 1024] + fb[base + 1024];
            float go = fa[base + 1536] + fb[base + 1536];
            c = sig_(gF) * c + sig_(gi) * th_(gg);
            float h = sig_(go) * th_(c);
            ((float*)hp)[base] = h;               // base == 4*ecol + 2*erp + elane
            out[((size_t)(b0 + er) * TT + t) * 128 + ecol] = h;
            if (t == TT - 1) hn[(size_t)(b0 + er) * 128 + ecol] = h;
        }
        __syncthreads();
    }
}

// ---------------------------------------------------------------------------
__global__ void transposeW3(const float* __restrict__ Whh, float* __restrict__ Wt)
{
    int i = blockIdx.x * 256 + threadIdx.x;
    if (i < 128 * 512) {
        int k = i >> 9, col = i & 511;
        Wt[i] = Whh[col * 128 + k];
    }
}

// ---------------------------------------------------------------------------
extern "C" void kernel_launch(void* const* d_in, const int* in_sizes, int n_in,
                              void* d_out, int out_size)
{
    const float* z    = (const float*)d_in[0];
    const float* Wih1 = (const float*)d_in[1];
    const float* Whh1 = (const float*)d_in[2];
    const float* bih1 = (const float*)d_in[3];
    const float* bhh1 = (const float*)d_in[4];
    const float* Wih2 = (const float*)d_in[5];
    const float* Whh2 = (const float*)d_in[6];
    const float* bih2 = (const float*)d_in[7];
    const float* bhh2 = (const float*)d_in[8];
    const float* Wih3 = (const float*)d_in[9];
    const float* Whh3 = (const float*)d_in[10];
    const float* bih3 = (const float*)d_in[11];
    const float* bhh3 = (const float*)d_in[12];

    float* dec = (float*)d_out;                        // [B,T,128]
    float* hn  = dec + (size_t)BB * TT * 128;          // [1,B,128]

    __half* gx;
    float *h1, *h2, *Wt3;
    cudaGetSymbolAddress((void**)&gx, g_gxh);
    cudaGetSymbolAddress((void**)&h1, g_h1);
    cudaGetSymbolAddress((void**)&h2, g_h2);
    cudaGetSymbolAddress((void**)&Wt3, g_Wt3);

    cudaFuncSetAttribute(lstm_recur_big,
                         cudaFuncAttributeMaxDynamicSharedMemorySize, SMEM_BIG);

    transposeW3<<<256, 256>>>(Whh3, Wt3);

    // Layer 1: 64 -> 32
    lstm_projM<64, 128><<<2048, 256>>>(z, Wih1, bih1, bhh1, gx);
    lstm_recur_small<32><<<BB / 4, 128>>>(gx, Whh1, h1);

    // Layer 2: 32 -> 48
    lstm_projM<32, 192><<<2048, 256>>>(h1, Wih2, bih2, bhh2, gx);
    lstm_recur_small<48><<<BB / 4, 192>>>(gx, Whh2, h2);

    // Layer 3: 48 -> 128
    lstm_projM<48, 512><<<2048, 256>>>(h2, Wih3, bih3, bhh3, gx);
    lstm_recur_big<<<BB / 4, 512, SMEM_BIG>>>(gx, Wt3, dec, hn);
}

// round 15
// speedup vs baseline: 1.9632x; 1.1141x over previous
#include <cuda_runtime.h>
#include <cuda_fp16.h>
#include <math.h>

#define BB 512
#define TT 512

// ---------------- device scratch (allocation-free rule) ----------------
__device__ __half g_gxh[(size_t)TT * BB * 512];   // gate pre-activations (fp16)
__device__ float  g_h1[(size_t)BB * TT * 32];     // layer1 output
__device__ float  g_h2[(size_t)BB * TT * 48];     // layer2 output

// ---------------- f32x2 helpers ----------------
__device__ __forceinline__ unsigned long long pk2(float a, float b) {
    unsigned long long r;
    asm("mov.b64 %0, {%1,%2};" : "=l"(r) : "f"(a), "f"(b));
    return r;
}
__device__ __forceinline__ void fma2_(unsigned long long& d, unsigned long long a,
                                      unsigned long long b) {
    asm("fma.rn.f32x2 %0, %1, %2, %0;" : "+l"(d) : "l"(a), "l"(b));
}
__device__ __forceinline__ unsigned long long add2_(unsigned long long a,
                                                    unsigned long long b) {
    unsigned long long r;
    asm("add.rn.f32x2 %0, %1, %2;" : "=l"(r) : "l"(a), "l"(b));
    return r;
}
__device__ __forceinline__ float sig_(float x) { return 1.0f / (1.0f + __expf(-x)); }
__device__ __forceinline__ float th_(float x) { return 1.0f - 2.0f / (__expf(2.0f * x) + 1.0f); }

// ---------------- mma helpers (verified R8/R13) ----------------
__device__ __forceinline__ unsigned smem_u32(const void* p) {
    return (unsigned)__cvta_generic_to_shared(p);
}
__device__ __forceinline__ void ldmx4(unsigned& a0, unsigned& a1, unsigned& a2,
                                      unsigned& a3, unsigned addr) {
    asm volatile("ldmatrix.sync.aligned.m8n8.x4.shared.b16 {%0,%1,%2,%3}, [%4];"
                 : "=r"(a0), "=r"(a1), "=r"(a2), "=r"(a3) : "r"(addr));
}
__device__ __forceinline__ void mma16816(float* d, unsigned a0, unsigned a1,
                                         unsigned a2, unsigned a3,
                                         unsigned b0, unsigned b1) {
    asm volatile(
        "mma.sync.aligned.m16n8k16.row.col.f32.f16.f16.f32 "
        "{%0,%1,%2,%3}, {%4,%5,%6,%7}, {%8,%9}, {%0,%1,%2,%3};"
        : "+f"(d[0]), "+f"(d[1]), "+f"(d[2]), "+f"(d[3])
        : "r"(a0), "r"(a1), "r"(a2), "r"(a3), "r"(b0), "r"(b1));
}

// ---------------------------------------------------------------------------
// Input projection via tensor cores, coalesced stores (R13-proven WIN).
// ---------------------------------------------------------------------------
template <int D, int N>
__global__ void __launch_bounds__(256)
lstm_projM(const float* __restrict__ xin, const float* __restrict__ Wih,
           const float* __restrict__ bih, const float* __restrict__ bhh,
           __half* __restrict__ gx)
{
    constexpr int KT = D / 16;
    constexpr int NTILES = N / 64;
    constexpr int NCW = N / 8;
    constexpr int XPAD = D + 8;
    constexpr int OPAD = N + 8;

    __shared__ __align__(16) __half xs[32][XPAD];
    __shared__ __align__(16) __half os[32][OPAD];

    const int tid = threadIdx.x;
    const int w = tid >> 5, l = tid & 31;
    const int l4 = l & 3, lq = l >> 2;
    const int wbase = w * NCW;

    unsigned bf[KT][NTILES][2];
#pragma unroll
    for (int kt = 0; kt < KT; kt++)
#pragma unroll
        for (int ti = 0; ti < NTILES; ti++) {
            int n = wbase + ti * 8 + lq;
            int k0 = kt * 16 + 2 * l4;
            __half2 v0 = __floats2half2_rn(__ldg(&Wih[n * D + k0]),
                                           __ldg(&Wih[n * D + k0 + 1]));
            __half2 v1 = __floats2half2_rn(__ldg(&Wih[n * D + k0 + 8]),
                                           __ldg(&Wih[n * D + k0 + 9]));
            bf[kt][ti][0] = *(unsigned*)&v0;
            bf[kt][ti][1] = *(unsigned*)&v1;
        }
    float2 b2[NTILES];
#pragma unroll
    for (int ti = 0; ti < NTILES; ti++) {
        int n0 = wbase + ti * 8 + 2 * l4;
        b2[ti] = make_float2(__ldg(&bih[n0]) + __ldg(&bhh[n0]),
                             __ldg(&bih[n0 + 1]) + __ldg(&bhh[n0 + 1]));
    }

    const int arow = l & 15, acg = (l >> 4) * 8;
    const int ntiles_tot = (BB * TT) / 32;

#pragma unroll 1
    for (int tile = blockIdx.x; tile < ntiles_tot; tile += gridDim.x) {
        __syncthreads();
#pragma unroll 1
        for (int i = tid; i < 32 * (D / 4); i += 256) {
            int row = i / (D / 4), k4 = i % (D / 4);
            float4 v = ((const float4*)(xin + (size_t)(tile * 32 + row) * D))[k4];
            *(__half2*)&xs[row][4 * k4]     = __floats2half2_rn(v.x, v.y);
            *(__half2*)&xs[row][4 * k4 + 2] = __floats2half2_rn(v.z, v.w);
        }
        __syncthreads();

#pragma unroll
        for (int mt = 0; mt < 2; mt++) {
            unsigned aa[KT][4];
#pragma unroll
            for (int kt = 0; kt < KT; kt++)
                ldmx4(aa[kt][0], aa[kt][1], aa[kt][2], aa[kt][3],
                      smem_u32(&xs[mt * 16 + arow][acg + 16 * kt]));

            float d[NTILES][4];
#pragma unroll
            for (int ti = 0; ti < NTILES; ti++) {
                d[ti][0] = b2[ti].x; d[ti][1] = b2[ti].y;
                d[ti][2] = b2[ti].x; d[ti][3] = b2[ti].y;
            }
#pragma unroll
            for (int kt = 0; kt < KT; kt++)
#pragma unroll
                for (int ti = 0; ti < NTILES; ti++)
                    mma16816(d[ti], aa[kt][0], aa[kt][1], aa[kt][2], aa[kt][3],
                             bf[kt][ti][0], bf[kt][ti][1]);

#pragma unroll
            for (int ti = 0; ti < NTILES; ti++)
#pragma unroll
                for (int rr = 0; rr < 2; rr++)
                    *(__half2*)&os[mt * 16 + lq + 8 * rr][wbase + ti * 8 + 2 * l4] =
                        __floats2half2_rn(d[ti][2 * rr], d[ti][2 * rr + 1]);
        }
        __syncthreads();

#pragma unroll 1
        for (int i = tid; i < 32 * (N / 8); i += 256) {
            int row = i / (N / 8), c8 = i % (N / 8);
            int m = tile * 32 + row;
            int b = m >> 9, t = m & 511;
            *(float4*)(gx + ((size_t)t * BB + b) * N + 8 * c8) =
                *(const float4*)&os[row][8 * c8];
        }
    }
}

// ---------------------------------------------------------------------------
// Small-layer recurrence (R14-proven), Bc=4, fp16 gx, depth-2 prefetch.
// ---------------------------------------------------------------------------
template <int H>
__global__ void __launch_bounds__(4 * H)
lstm_recur_small(const __half* __restrict__ gx,  // [T][B][4H] fp16
                 const float* __restrict__ Whh,  // [4H][H]
                 float* __restrict__ out)        // [B][T][H]
{
    constexpr int G = 4 * H;
    const int col = threadIdx.x;
    const int b0 = blockIdx.x * 4;

    unsigned long long wh2[H];
#pragma unroll
    for (int k = 0; k < H; k++) {
        float w = __ldg(&Whh[col * H + k]);
        wh2[k] = pk2(w, w);
    }

    __shared__ __align__(16) unsigned long long h2[H][2];
    __shared__ __align__(16) unsigned long long g2[G][2];
    ((float*)h2)[col] = 0.f;

    const int hcol = col >> 2, er = col & 3;
    const int erp = er >> 1, elane = er & 1;
    float c = 0.f;

    const __half* gbase = gx + (size_t)b0 * G + col;
    const size_t ts = (size_t)BB * G;

    __half A0 = gbase[0], A1 = gbase[G], A2 = gbase[2 * G], A3 = gbase[3 * G];
    __half B0 = gbase[ts], B1 = gbase[ts + G], B2 = gbase[ts + 2 * G], B3 = gbase[ts + 3 * G];
    __syncthreads();

    const ulonglong2* hp2 = (const ulonglong2*)h2;

    for (int t = 0; t < TT; t++) {
        __half C0 = __float2half(0.f), C1 = C0, C2 = C0, C3 = C0;
        if (t + 2 < TT) {
            const __half* gp = gbase + (size_t)(t + 2) * ts;
            C0 = gp[0]; C1 = gp[G]; C2 = gp[2 * G]; C3 = gp[3 * G];
        }
        unsigned long long a00 = 0, a01 = 0, a10 = 0, a11 = 0;
#pragma unroll
        for (int k = 0; k < H; k += 2) {
            ulonglong2 ha = hp2[k];
            ulonglong2 hb = hp2[k + 1];
            fma2_(a00, wh2[k], ha.x);     fma2_(a01, wh2[k], ha.y);
            fma2_(a10, wh2[k + 1], hb.x); fma2_(a11, wh2[k + 1], hb.y);
        }
        ulonglong2 s;
        s.x = add2_(add2_(a00, a10), pk2(__half2float(A0), __half2float(A1)));
        s.y = add2_(add2_(a01, a11), pk2(__half2float(A2), __half2float(A3)));
        ((ulonglong2*)g2)[col] = s;
        A0 = B0; A1 = B1; A2 = B2; A3 = B3;
        B0 = C0; B1 = C1; B2 = C2; B3 = C3;
        __syncthreads();

        {
            const float* gf = (const float*)g2;
            int base = 4 * hcol + 2 * erp + elane;
            float gi = gf[base];
            float gF = gf[base + 4 * H];
            float gg = gf[base + 8 * H];
            float go = gf[base + 12 * H];
            c = sig_(gF) * c + sig_(gi) * th_(gg);
            float h = sig_(go) * th_(c);
            ((float*)h2)[base] = h;
            out[((size_t)(b0 + er) * TT + t) * H + hcol] = h;
        }
        __syncthreads();
    }
}

// ---------------------------------------------------------------------------
// Layer-3 recurrence: 4-CTA cluster, tensor-core mma (fp16 in, fp32 accum).
// Cluster owns 16 batch rows; CTA rank r owns h-cols [32r,32r+32).
// Warp w owns h-cols [32r+8w, 32r+8w+8) -> n-tiles {i,f,g,o} at 128g+32r+8w.
// Whh3 lives in B-fragments in registers. h (fp16) double-buffered in every
// CTA's smem; each CTA broadcasts its 32-col slice via st.shared::cluster.
// ONE barrier.cluster per step.
// ---------------------------------------------------------------------------
#define CLUSTER 4
#define HPAD 136   // half stride per h row (272B -> conflict-free ldmatrix)

__global__ void __launch_bounds__(128, 1) __cluster_dims__(CLUSTER, 1, 1)
lstm_recur_cluster(const __half* __restrict__ gx,   // [T][B][512] fp16
                   const float* __restrict__ Whh,   // [512][128] Whh3
                   float* __restrict__ out,         // [B][T][128]
                   float* __restrict__ hn)          // [B][128]
{
    __shared__ __align__(16) __half hsm[2][16][HPAD];

    const int tid = threadIdx.x;
    const int w = tid >> 5, l = tid & 31;
    const int l4 = l & 3, lq = l >> 2;
    unsigned rank;
    asm("mov.u32 %0, %%cluster_ctarank;" : "=r"(rank));
    const int b0 = (blockIdx.x >> 2) * 16;
    const int hbase = 32 * (int)rank + 8 * w;    // this warp's h-col base

    // ---- B fragments: Whh3 register-resident (n = 128*g + hbase + lq) ----
    unsigned bf[8][4][2];
#pragma unroll
    for (int kt = 0; kt < 8; kt++)
#pragma unroll
        for (int g = 0; g < 4; g++) {
            int n = 128 * g + hbase + lq;
            int k0 = 16 * kt + 2 * l4;
            __half2 v0 = __floats2half2_rn(__ldg(&Whh[n * 128 + k0]),
                                           __ldg(&Whh[n * 128 + k0 + 1]));
            __half2 v1 = __floats2half2_rn(__ldg(&Whh[n * 128 + k0 + 8]),
                                           __ldg(&Whh[n * 128 + k0 + 9]));
            bf[kt][g][0] = *(unsigned*)&v0;
            bf[kt][g][1] = *(unsigned*)&v1;
        }

    // zero buffer 1 (read at t=0); buffer 0 fully overwritten before t=1 read
    for (int i = tid; i < 16 * HPAD / 2; i += 128)
        ((unsigned*)&hsm[1][0][0])[i] = 0u;

    // peer smem bases (DSMEM window is linear per CTA)
    unsigned mybase = smem_u32(&hsm[0][0][0]);
    unsigned peer[CLUSTER];
#pragma unroll
    for (int r = 0; r < CLUSTER; r++)
        asm("mapa.shared::cluster.u32 %0, %1, %2;" : "=r"(peer[r]) : "r"(mybase), "r"(r));

    __syncthreads();
    asm volatile("barrier.cluster.arrive.aligned;" ::: "memory");
    asm volatile("barrier.cluster.wait.aligned;" ::: "memory");

    float c[4];
#pragma unroll
    for (int i = 0; i < 4; i++) c[i] = 0.f;

    const int arow = l & 15, acg = (l >> 4) * 8;

    // gx fragment loads: (g, rr) -> half2 at row b0+lq+8rr, col 128g+hbase+2l4
    unsigned gxf[8];
    {
        const __half* gp = gx + ((size_t)0 * BB + (b0 + lq)) * 512 + hbase + 2 * l4;
#pragma unroll
        for (int g = 0; g < 4; g++)
#pragma unroll
            for (int rr = 0; rr < 2; rr++)
                gxf[g * 2 + rr] = *(const unsigned*)(gp + g * 128 + rr * 8 * 512);
    }

    for (int t = 0; t < TT; t++) {
        const int rb = (t + 1) & 1;     // read h written at t-1
        const int wb = t & 1;

        // prefetch next step's gx (latency hidden under mma)
        unsigned gxn[8];
        if (t + 1 < TT) {
            const __half* gp = gx + ((size_t)(t + 1) * BB + (b0 + lq)) * 512 + hbase + 2 * l4;
#pragma unroll
            for (int g = 0; g < 4; g++)
#pragma unroll
                for (int rr = 0; rr < 2; rr++)
                    gxn[g * 2 + rr] = *(const unsigned*)(gp + g * 128 + rr * 8 * 512);
        }

        // accumulators initialized with gx
        float d[4][4];
#pragma unroll
        for (int g = 0; g < 4; g++)
#pragma unroll
            for (int rr = 0; rr < 2; rr++) {
                float2 f = __half22float2(*(__half2*)&gxf[g * 2 + rr]);
                d[g][2 * rr + 0] = f.x;
                d[g][2 * rr + 1] = f.y;
            }

#pragma unroll
        for (int kt = 0; kt < 8; kt++) {
            unsigned a0, a1, a2, a3;
            ldmx4(a0, a1, a2, a3, smem_u32(&hsm[rb][arow][acg + 16 * kt]));
#pragma unroll
            for (int g = 0; g < 4; g++)
                mma16816(d[g], a0, a1, a2, a3, bf[kt][g][0], bf[kt][g][1]);
        }

        // epilogue: 4 cells/thread (rows lq, lq+8; cols hbase+2l4, +1)
        float h[4];
#pragma unroll
        for (int reg = 0; reg < 4; reg++) {
            float gi = d[0][reg], gF = d[1][reg], gg = d[2][reg], go = d[3][reg];
            c[reg] = sig_(gF) * c[reg] + sig_(gi) * th_(gg);
            h[reg] = sig_(go) * th_(c[reg]);
        }
        __half2 hA = __floats2half2_rn(h[0], h[1]);   // row lq
        __half2 hB = __floats2half2_rn(h[2], h[3]);   // row lq+8
        unsigned offA = ((wb * 16 + lq) * HPAD + hbase + 2 * l4) * 2;
        unsigned offB = ((wb * 16 + lq + 8) * HPAD + hbase + 2 * l4) * 2;
        unsigned hA32 = *(unsigned*)&hA, hB32 = *(unsigned*)&hB;
#pragma unroll
        for (int r = 0; r < CLUSTER; r++) {
            asm volatile("st.shared::cluster.u32 [%0], %1;" :: "r"(peer[r] + offA), "r"(hA32) : "memory");
            asm volatile("st.shared::cluster.u32 [%0], %1;" :: "r"(peer[r] + offB), "r"(hB32) : "memory");
        }
        asm volatile("barrier.cluster.arrive.aligned;" ::: "memory");

        // gmem stores overlap the barrier wait
        {
            int hc = hbase + 2 * l4;
            *(float2*)(out + ((size_t)(b0 + lq) * TT + t) * 128 + hc) = make_float2(h[0], h[1]);
            *(float2*)(out + ((size_t)(b0 + lq + 8) * TT + t) * 128 + hc) = make_float2(h[2], h[3]);
            if (t == TT - 1) {
                *(float2*)(hn + (size_t)(b0 + lq) * 128 + hc) = make_float2(h[0], h[1]);
                *(float2*)(hn + (size_t)(b0 + lq + 8) * 128 + hc) = make_float2(h[2], h[3]);
            }
        }
#pragma unroll
        for (int i = 0; i < 8; i++) gxf[i] = gxn[i];

        asm volatile("barrier.cluster.wait.aligned;" ::: "memory");
    }
}

// ---------------------------------------------------------------------------
extern "C" void kernel_launch(void* const* d_in, const int* in_sizes, int n_in,
                              void* d_out, int out_size)
{
    const float* z    = (const float*)d_in[0];
    const float* Wih1 = (const float*)d_in[1];
    const float* Whh1 = (const float*)d_in[2];
    const float* bih1 = (const float*)d_in[3];
    const float* bhh1 = (const float*)d_in[4];
    const float* Wih2 = (const float*)d_in[5];
    const float* Whh2 = (const float*)d_in[6];
    const float* bih2 = (const float*)d_in[7];
    const float* bhh2 = (const float*)d_in[8];
    const float* Wih3 = (const float*)d_in[9];
    const float* Whh3 = (const float*)d_in[10];
    const float* bih3 = (const float*)d_in[11];
    const float* bhh3 = (const float*)d_in[12];

    float* dec = (float*)d_out;                        // [B,T,128]
    float* hn  = dec + (size_t)BB * TT * 128;          // [1,B,128]

    __half* gx;
    float *h1, *h2;
    cudaGetSymbolAddress((void**)&gx, g_gxh);
    cudaGetSymbolAddress((void**)&h1, g_h1);
    cudaGetSymbolAddress((void**)&h2, g_h2);

    // Layer 1: 64 -> 32
    lstm_projM<64, 128><<<2048, 256>>>(z, Wih1, bih1, bhh1, gx);
    lstm_recur_small<32><<<BB / 4, 128>>>(gx, Whh1, h1);

    // Layer 2: 32 -> 48
    lstm_projM<32, 192><<<2048, 256>>>(h1, Wih2, bih2, bhh2, gx);
    lstm_recur_small<48><<<BB / 4, 192>>>(gx, Whh2, h2);

    // Layer 3: 48 -> 128
    lstm_projM<48, 512><<<2048, 256>>>(h2, Wih3, bih3, bhh3, gx);
    lstm_recur_cluster<<<BB / 16 * CLUSTER, 128>>>(gx, Whh3, dec, hn);
}